// round 2
// baseline (speedup 1.0000x reference)
#include <cuda_runtime.h>

// TrueHigherOrderAttention — degenerate-mask reduction (see R1: mask is one-hot
// at i==j==k, so  out = ((x @ Wv1^T) .* (x @ Wv2^T)) @ Wc^T ).
//
// R2: f32x2 packed FMA (SASS FFMA2 via PTX fma.rn.f32x2), broadcast-duplicated
// X tiles in smem (zero pack-movs), k-major transposed tiles, register-staged
// global prefetch.

constexpr int T  = 256;
constexpr int C  = 512;
constexpr int K  = 512;
constexpr int KC = 64;          // K chunk
constexpr int NCH = K / KC;     // 8 chunks

__device__ float g_tmp[T * C];

__device__ __forceinline__ float2 fma2(float2 d, float2 a, float2 b)
{
    unsigned long long dd, aa, bb;
    dd = *reinterpret_cast<unsigned long long*>(&d);
    aa = *reinterpret_cast<unsigned long long*>(&a);
    bb = *reinterpret_cast<unsigned long long*>(&b);
    asm("fma.rn.f32x2 %0, %1, %2, %0;" : "+l"(dd) : "l"(aa), "l"(bb));
    return *reinterpret_cast<float2*>(&dd);
}

// OUT = (X @ W1^T) [ .* (X @ W2^T) if DUAL ]
// X: [M x C] row-major; W: [C x C] row-major (output col n = row n of W).
// CTA tile: 32 rows x 32 cols. 256 threads; each owns a 2x2 microtile
// (rows 2ty,2ty+1; cols 2tx,2tx+1) held as f32x2 column-pairs.
template <bool DUAL>
__global__ __launch_bounds__(256)
void gemm2_kernel(const float* __restrict__ X,
                  const float* __restrict__ W1,
                  const float* __restrict__ W2,
                  float* __restrict__ OUT)
{
    // k-major tiles. xs holds each X value DUPLICATED: xs[k][2r]=xs[k][2r+1]=X[r][k]
    // so one LDS.128 at [k][4*ty] yields both broadcast pairs for rows 2ty,2ty+1.
    __shared__ float xs [KC][64];               // 16 KB
    __shared__ float w1s[KC][32];               //  8 KB
    __shared__ float w2s[DUAL ? KC : 1][32];    //  8 KB (DUAL only)

    const int i0  = blockIdx.x * 32;            // row block in [0,T)
    const int n0  = blockIdx.y * 32;            // col block in [0,C)
    const int tid = threadIdx.x;
    const int tx  = tid & 15;                   // col-pair index
    const int ty  = tid >> 4;                   // row-pair index

    // Loader mapping: lanes within a warp differ by ROW (not k) so the
    // transposed STS pattern is (near) conflict-free; the strided LDGs stay
    // L2-resident (whole working set ~3.5 MB).
    const int lrow = tid & 31;                  // 0..31
    const int lc0  = (tid >> 5) << 2;           // 0,4,...,28

    float4 xr[2], w1r[2], w2r[2];

    auto gload = [&](int kc) {
#pragma unroll
        for (int it = 0; it < 2; it++) {
            const int c4 = lc0 + 32 * it;       // 0..60 step 4
            xr [it] = *(const float4*)&X [(i0 + lrow) * C + kc + c4];
            w1r[it] = *(const float4*)&W1[(n0 + lrow) * C + kc + c4];
            if (DUAL)
                w2r[it] = *(const float4*)&W2[(n0 + lrow) * C + kc + c4];
        }
    };

    gload(0);

    float2 p0 = make_float2(0.f, 0.f), p1 = p0, q0 = p0, q1 = p0;

    for (int ch = 0; ch < NCH; ch++) {
        __syncthreads();
        // Stage registers -> smem (transposed, X duplicated)
#pragma unroll
        for (int it = 0; it < 2; it++) {
            const int c4 = lc0 + 32 * it;
            const float xv [4] = {xr [it].x, xr [it].y, xr [it].z, xr [it].w};
            const float w1v[4] = {w1r[it].x, w1r[it].y, w1r[it].z, w1r[it].w};
#pragma unroll
            for (int j = 0; j < 4; j++) {
                *(float2*)&xs[c4 + j][2 * lrow] = make_float2(xv[j], xv[j]);
                w1s[c4 + j][lrow] = w1v[j];
            }
            if (DUAL) {
                const float w2v[4] = {w2r[it].x, w2r[it].y, w2r[it].z, w2r[it].w};
#pragma unroll
                for (int j = 0; j < 4; j++)
                    w2s[c4 + j][lrow] = w2v[j];
            }
        }
        __syncthreads();

        // Prefetch next chunk while computing this one (hidden under ~1K cyc).
        if (ch + 1 < NCH) gload((ch + 1) * KC);

#pragma unroll
        for (int k = 0; k < KC; k++) {
            const float4 a  = *(const float4*)&xs[k][4 * ty];   // {a0,a0,a1,a1}
            const float2 b1 = *(const float2*)&w1s[k][2 * tx];
            const float2 a01 = make_float2(a.x, a.y);
            const float2 a23 = make_float2(a.z, a.w);
            p0 = fma2(p0, a01, b1);
            p1 = fma2(p1, a23, b1);
            if (DUAL) {
                const float2 b2 = *(const float2*)&w2s[k][2 * tx];
                q0 = fma2(q0, a01, b2);
                q1 = fma2(q1, a23, b2);
            }
        }
    }

    float2 r0 = p0, r1 = p1;
    if (DUAL) {
        r0.x = p0.x * q0.x;  r0.y = p0.y * q0.y;
        r1.x = p1.x * q1.x;  r1.y = p1.y * q1.y;
    }
    *(float2*)&OUT[(i0 + 2 * ty    ) * C + n0 + 2 * tx] = r0;
    *(float2*)&OUT[(i0 + 2 * ty + 1) * C + n0 + 2 * tx] = r1;
}

extern "C" void kernel_launch(void* const* d_in, const int* in_sizes, int n_in,
                              void* d_out, int out_size)
{
    // metadata order: x, Wq, Wk1, Wk2, Wv1, Wv2, Wc
    const float* x   = (const float*)d_in[0];
    const float* Wv1 = (const float*)d_in[4];
    const float* Wv2 = (const float*)d_in[5];
    const float* Wc  = (const float*)d_in[6];
    float* out = (float*)d_out;

    float* tmp = nullptr;
    cudaGetSymbolAddress((void**)&tmp, g_tmp);

    dim3 grid(T / 32, C / 32);   // 8 x 16 = 128 CTAs (~1 wave on 148 SMs)
    gemm2_kernel<true ><<<grid, 256>>>(x,   Wv1, Wv2,     tmp);
    gemm2_kernel<false><<<grid, 256>>>(tmp, Wc,  nullptr, out);
}

// round 3
// speedup vs baseline: 1.3655x; 1.3655x over previous
#include <cuda_runtime.h>

// TrueHigherOrderAttention — degenerate-mask reduction.
// Mask requires j==i and k==i => softmax is an exact one-hot at (i,i,i):
//   out = ((x @ Wv1^T) .* (x @ Wv2^T)) @ Wc^T
//
// R3: 2x4 microtile (8 FMA : 3 LDS mix), in-CTA split-K (two 128-thread
// halves each cover the full 32x32 tile over half of K; smem reduction
// epilogue), k-major smem tiles with conflict-free transposed stores,
// register-staged global prefetch. Scalar FFMA only.

constexpr int T   = 256;
constexpr int C   = 512;
constexpr int K   = 512;
constexpr int KC  = 64;        // k chunk per smem stage
constexpr int NCH = K / KC;    // 8

__device__ float g_tmp[T * C];

// OUT = (X @ W1^T) [ .* (X @ W2^T) if DUAL ]
// X: [M x C] row-major; W: [C x C] row-major (output col n = row n of W).
// CTA: 32 rows x 32 cols, 256 threads. half = tid>>7 picks K half.
// Within a half: tx=htid&7 -> cols 4tx..4tx+3 ; ty=htid>>3 -> rows 2ty,2ty+1.
template <bool DUAL>
__global__ __launch_bounds__(256)
void gemm_kernel(const float* __restrict__ X,
                 const float* __restrict__ W1,
                 const float* __restrict__ W2,
                 float* __restrict__ OUT)
{
    __shared__ float xs [KC][32];                 // k-major: xs[k][row]
    __shared__ float w1s[KC][32];                 // w1s[k][col]
    __shared__ float w2s[DUAL ? KC : 1][32];
    __shared__ float red[128][DUAL ? 20 : 12];    // reduction pad (16B-aligned rows)

    const int i0   = blockIdx.x * 32;
    const int n0   = blockIdx.y * 32;
    const int tid  = threadIdx.x;
    const int half = tid >> 7;       // 0: k in [0,32) of chunk, 1: [32,64)
    const int htid = tid & 127;
    const int tx   = htid & 7;
    const int ty   = htid >> 3;

    // Loader mapping: lane varies by ROW -> transposed STS is conflict-free.
    const int lr = tid & 31;         // tile row (X) / tile col (W)
    const int lc = tid >> 5;         // 0..7 -> float4 cols {4lc, 4lc+32}

    float4 xr[2], w1r[2], w2r[2];
    auto gload = [&](int kc) {
#pragma unroll
        for (int it = 0; it < 2; it++) {
            const int c4 = 4 * lc + 32 * it;
            xr [it] = *(const float4*)&X [(i0 + lr) * C + kc + c4];
            w1r[it] = *(const float4*)&W1[(n0 + lr) * C + kc + c4];
            if (DUAL)
                w2r[it] = *(const float4*)&W2[(n0 + lr) * C + kc + c4];
        }
    };
    gload(0);

    float p[2][4] = {}, q[2][4] = {};

    for (int ch = 0; ch < NCH; ch++) {
        __syncthreads();
        // Transposed stores: addr = (c4+j)*32 + lr -> banks = lr (conflict-free)
#pragma unroll
        for (int it = 0; it < 2; it++) {
            const int c4 = 4 * lc + 32 * it;
            const float xv [4] = {xr [it].x, xr [it].y, xr [it].z, xr [it].w};
            const float w1v[4] = {w1r[it].x, w1r[it].y, w1r[it].z, w1r[it].w};
#pragma unroll
            for (int j = 0; j < 4; j++) {
                xs [c4 + j][lr] = xv [j];
                w1s[c4 + j][lr] = w1v[j];
            }
            if (DUAL) {
                const float w2v[4] = {w2r[it].x, w2r[it].y, w2r[it].z, w2r[it].w};
#pragma unroll
                for (int j = 0; j < 4; j++)
                    w2s[c4 + j][lr] = w2v[j];
            }
        }
        __syncthreads();

        if (ch + 1 < NCH) gload((ch + 1) * KC);   // prefetch under compute

        const int kb = half * 32;
#pragma unroll
        for (int kk = 0; kk < 32; kk++) {
            const int k = kb + kk;
            const float2 a  = *(const float2*)&xs [k][2 * ty];  // broadcast-y
            const float4 b1 = *(const float4*)&w1s[k][4 * tx];
            p[0][0] += a.x * b1.x;  p[0][1] += a.x * b1.y;
            p[0][2] += a.x * b1.z;  p[0][3] += a.x * b1.w;
            p[1][0] += a.y * b1.x;  p[1][1] += a.y * b1.y;
            p[1][2] += a.y * b1.z;  p[1][3] += a.y * b1.w;
            if (DUAL) {
                const float4 b2 = *(const float4*)&w2s[k][4 * tx];
                q[0][0] += a.x * b2.x;  q[0][1] += a.x * b2.y;
                q[0][2] += a.x * b2.z;  q[0][3] += a.x * b2.w;
                q[1][0] += a.y * b2.x;  q[1][1] += a.y * b2.y;
                q[1][2] += a.y * b2.z;  q[1][3] += a.y * b2.w;
            }
        }
    }

    // Merge halves: half 1 dumps partials, half 0 reduces, multiplies, stores.
    __syncthreads();
    if (half == 1) {
#pragma unroll
        for (int r = 0; r < 2; r++) {
            *(float4*)&red[htid][4 * r] = *(float4*)&p[r][0];
            if (DUAL) *(float4*)&red[htid][8 + 4 * r] = *(float4*)&q[r][0];
        }
    }
    __syncthreads();
    if (half == 0) {
#pragma unroll
        for (int r = 0; r < 2; r++) {
            const float4 po = *(const float4*)&red[htid][4 * r];
            float4 res;
            if (DUAL) {
                const float4 qo = *(const float4*)&red[htid][8 + 4 * r];
                res.x = (p[r][0] + po.x) * (q[r][0] + qo.x);
                res.y = (p[r][1] + po.y) * (q[r][1] + qo.y);
                res.z = (p[r][2] + po.z) * (q[r][2] + qo.z);
                res.w = (p[r][3] + po.w) * (q[r][3] + qo.w);
            } else {
                res.x = p[r][0] + po.x;  res.y = p[r][1] + po.y;
                res.z = p[r][2] + po.z;  res.w = p[r][3] + po.w;
            }
            *(float4*)&OUT[(i0 + 2 * ty + r) * C + n0 + 4 * tx] = res;
        }
    }
}

extern "C" void kernel_launch(void* const* d_in, const int* in_sizes, int n_in,
                              void* d_out, int out_size)
{
    // metadata order: x, Wq, Wk1, Wk2, Wv1, Wv2, Wc
    const float* x   = (const float*)d_in[0];
    const float* Wv1 = (const float*)d_in[4];
    const float* Wv2 = (const float*)d_in[5];
    const float* Wc  = (const float*)d_in[6];
    float* out = (float*)d_out;

    float* tmp = nullptr;
    cudaGetSymbolAddress((void**)&tmp, g_tmp);

    dim3 grid(T / 32, C / 32);   // 8 x 16 = 128 CTAs
    gemm_kernel<true ><<<grid, 256>>>(x,   Wv1, Wv2,     tmp);
    gemm_kernel<false><<<grid, 256>>>(tmp, Wc,  nullptr, out);
}